// round 2
// baseline (speedup 1.0000x reference)
#include <cuda_runtime.h>
#include <cuda_bf16.h>
#include <stdint.h>

// ---------------- configuration ----------------
#define THREADS        256
#define ITERS          8
#define TILE           (THREADS * ITERS)    // 2048 rows per block
#define MAXB           16384                // supports R up to 32M
#define SCORE_THRESHOLD 0.35f

// ---------------- device scratch (no allocs allowed) ----------------
// status word: bits[31:30] = 0 invalid, 1 aggregate-ready, 2 prefix-ready
//              bits[29:0]  = count (n <= R < 2^30)
__device__ unsigned g_stat [MAXB];
__device__ unsigned g_statF[MAXB];
__device__ int      g_total[2];

// ---------------- K0: clear lookback state ----------------
__global__ void init_kernel(int B) {
    int i = blockIdx.x * blockDim.x + threadIdx.x;
    if (i < B) { g_stat[i] = 0u; g_statF[i] = 0u; }
}

// ---------------- K1: fused count + lookback-scan + stable scatter ----------------
__global__ void __launch_bounds__(THREADS)
fused_kernel(const float2* __restrict__ det2, float* __restrict__ out,
             int R, unsigned roisN, int B) {
    __shared__ float2   srow[TILE * 3];         // 48 KB row cache
    __shared__ unsigned sm [ITERS][8], smF [ITERS][8];
    __shared__ unsigned co [ITERS][8], coF [ITERS][8];

    int b = blockIdx.x, t = threadIdx.x;
    int lane = t & 31, warp = t >> 5;
    unsigned ltmask = (1u << lane) - 1u;
    int base = b * TILE;

    // -------- phase 1: load tile into smem, ballot predicates --------
#pragma unroll
    for (int k = 0; k < ITERS; k++) {
        int idx = base + k * THREADS + t;
        float2 p0 = make_float2(1.f, 0.f);
        float2 p1 = make_float2(0.f, 0.f);
        float2 p2 = make_float2(0.f, -1.f);
        if (idx < R) {
            const float2* r = det2 + (size_t)idx * 3;
            p0 = r[0]; p1 = r[1]; p2 = r[2];
        }
        int lr = k * THREADS + t;
        srow[lr * 3 + 0] = p0;
        srow[lr * 3 + 1] = p1;
        srow[lr * 3 + 2] = p2;
        // row = [cls, b0, b1, b2, b3, score]
        bool predF = (idx < R) && (p2.y >= SCORE_THRESHOLD);
        bool pred  = predF && (p0.x == 0.0f);
        unsigned m  = __ballot_sync(0xffffffffu, pred);
        unsigned mF = __ballot_sync(0xffffffffu, predF);
        if (lane == 0) { sm[k][warp] = m; smF[k][warp] = mF; }
    }
    __syncthreads();

    // -------- phase 2: thread 0 does totals + decoupled lookback --------
    if (t == 0) {
        unsigned agg = 0, aggF = 0;
#pragma unroll
        for (int k = 0; k < ITERS; k++)
#pragma unroll
            for (int w = 0; w < 8; w++) {
                agg  += __popc(sm[k][w]);
                aggF += __popc(smF[k][w]);
            }
        unsigned excl = 0, exclF = 0;
        if (b == 0) {
            atomicExch(&g_stat [0], (2u << 30) | agg);
            atomicExch(&g_statF[0], (2u << 30) | aggF);
        } else {
            atomicExch(&g_stat [b], (1u << 30) | agg);
            atomicExch(&g_statF[b], (1u << 30) | aggF);
            // lookback: target counter
            for (int i = b - 1; ; i--) {
                unsigned s;
                do { s = *(volatile unsigned*)&g_stat[i]; } while ((s >> 30) == 0u);
                excl += s & 0x3FFFFFFFu;
                if ((s >> 30) == 2u) break;
            }
            atomicExch(&g_stat[b], (2u << 30) | (excl + agg));
            // lookback: full counter
            for (int i = b - 1; ; i--) {
                unsigned s;
                do { s = *(volatile unsigned*)&g_statF[i]; } while ((s >> 30) == 0u);
                exclF += s & 0x3FFFFFFFu;
                if ((s >> 30) == 2u) break;
            }
            atomicExch(&g_statF[b], (2u << 30) | (exclF + aggF));
        }
        // per-chunk offsets in row order (k-major, then warp)
        unsigned run = excl, runF = exclF;
#pragma unroll
        for (int k = 0; k < ITERS; k++)
#pragma unroll
            for (int w = 0; w < 8; w++) {
                co [k][w] = run;  run  += __popc(sm [k][w]);
                coF[k][w] = runF; runF += __popc(smF[k][w]);
            }
        if (b == B - 1) {
            g_total[0] = (int)run;
            g_total[1] = (int)runF;
            // n, n_full live right after the two ROI regions (11R floats)
            float* tail = out + (size_t)roisN + (size_t)roisN / 5u * 6u;
            tail[0] = (float)run;
            tail[1] = (float)runF;
        }
    }
    __syncthreads();

    // -------- phase 3: stable scatter from smem --------
    float* __restrict__ outFull = out + roisN;
#pragma unroll
    for (int k = 0; k < ITERS; k++) {
        unsigned m  = sm [k][warp];
        unsigned mF = smF[k][warp];
        bool predF = (mF >> lane) & 1u;
        if (predF) {
            int lr = k * THREADS + t;
            float2 p0 = srow[lr * 3 + 0];
            float2 p1 = srow[lr * 3 + 1];
            float2 p2 = srow[lr * 3 + 2];
            unsigned posF = coF[k][warp] + __popc(mF & ltmask);
            float2* oF = reinterpret_cast<float2*>(outFull) + (size_t)posF * 3;
            oF[0] = p0; oF[1] = p1; oF[2] = p2;
            if ((m >> lane) & 1u) {
                unsigned pos = co[k][warp] + __popc(m & ltmask);
                float* o = out + (size_t)pos * 5;
                o[0] = 0.0f;
                o[1] = p0.y; o[2] = p1.x; o[3] = p1.y; o[4] = p2.x;
            }
        }
    }
}

// ---------------- K2: zero the dynamic tails ----------------
// Each block owns 4096 contiguous floats (1024 quads, 4 quads/thread strided).
// All math 32-bit; 5R and 6R are multiples of 4 so full quads except at the
// n*5 / n_full*6 boundary (<=3 scalars, handled by the single straddling thread).
__global__ void zero_tail_kernel(float* __restrict__ out, unsigned R) {
    unsigned roisN = 5u * R;
    unsigned fullN = 6u * R;
    unsigned blockBase = blockIdx.x * 4096u;
    const float4 z4 = make_float4(0.f, 0.f, 0.f, 0.f);

#pragma unroll
    for (int j = 0; j < 4; j++) {
        unsigned f = blockBase + (unsigned)j * 1024u + threadIdx.x * 4u;
        if (f < roisN) {
            unsigned zs = (unsigned)g_total[0] * 5u;
            if (f + 4u <= zs) continue;
            if (f >= zs) {
                *reinterpret_cast<float4*>(out + f) = z4;
            } else {
                for (unsigned x = zs; x < f + 4u; x++) out[x] = 0.0f;
            }
        } else {
            unsigned g = f - roisN;
            if (g >= fullN) continue;
            unsigned zs = (unsigned)g_total[1] * 6u;
            if (g + 4u <= zs) continue;
            float* o = out + roisN;
            if (g >= zs) {
                *reinterpret_cast<float4*>(o + g) = z4;
            } else {
                for (unsigned x = zs; x < g + 4u; x++) o[x] = 0.0f;
            }
        }
    }
}

// ---------------- launch ----------------
extern "C" void kernel_launch(void* const* d_in, const int* in_sizes, int n_in,
                              void* d_out, int out_size) {
    const float* det = (const float*)d_in[0];
    float* out = (float*)d_out;

    int R = in_sizes[0] / 6;                 // detections: (1, R, 6)
    int B = (R + TILE - 1) / TILE;
    unsigned roisN = 5u * (unsigned)R;

    init_kernel<<<(B + 255) / 256, 256>>>(B);
    fused_kernel<<<B, THREADS>>>((const float2*)det, out, R, roisN, B);

    unsigned totalFloats = 11u * (unsigned)R;
    unsigned zblocks = (totalFloats + 4095u) / 4096u;
    zero_tail_kernel<<<zblocks, 256>>>(out, (unsigned)R);
}

// round 3
// speedup vs baseline: 1.6959x; 1.6959x over previous
#include <cuda_runtime.h>
#include <cuda_bf16.h>
#include <stdint.h>

// ---------------- configuration ----------------
#define THREADS   256
#define TILE      2048                 // rows per block (all kernels agree)
#define ITERS     8                    // TILE / THREADS
#define PAIRS     4                    // row-pairs per thread in count (4*2*256 = 2048)
#define MAXB      16384                // supports R up to 32M
#define SCAN_T    1024
#define SCORE_THRESHOLD 0.35f

// ---------------- device scratch ----------------
__device__ int g_cnt [MAXB];
__device__ int g_cntF[MAXB];
__device__ int g_off [MAXB];
__device__ int g_offF[MAXB];
__device__ int g_total[2];

// ---------------- K1: per-block counts (float4 streaming) ----------------
__global__ void __launch_bounds__(THREADS)
count_kernel(const float4* __restrict__ q, int R) {
    int b = blockIdx.x, t = threadIdx.x;
    // block covers rows [b*TILE, b*TILE+TILE) = pairs [b*1024, b*1024+1024)
    int pairBase = b * (TILE / 2);
    int c = 0, cF = 0;
#pragma unroll
    for (int k = 0; k < PAIRS; k++) {
        int p = pairBase + k * THREADS + t;         // pair index
        int r0 = p * 2;
        if (r0 < R) {
            const float4* g = q + (size_t)p * 3;
            float4 q0 = __ldg(g + 0);
            float4 q1 = __ldg(g + 1);
            float4 q2 = __ldg(g + 2);
            // row0: cls=q0.x score=q1.y ; row1: cls=q1.z score=q2.w
            bool f0 = (q1.y >= SCORE_THRESHOLD);
            bool f1 = (r0 + 1 < R) && (q2.w >= SCORE_THRESHOLD);
            cF += (f0 ? 1 : 0) + (f1 ? 1 : 0);
            c  += ((f0 && q0.x == 0.0f) ? 1 : 0) + ((f1 && q1.z == 0.0f) ? 1 : 0);
        }
    }
#pragma unroll
    for (int o = 16; o > 0; o >>= 1) {
        c  += __shfl_down_sync(0xffffffffu, c,  o);
        cF += __shfl_down_sync(0xffffffffu, cF, o);
    }
    __shared__ int sw[8], swF[8];
    int lane = t & 31, warp = t >> 5;
    if (lane == 0) { sw[warp] = c; swF[warp] = cF; }
    __syncthreads();
    if (t == 0) {
        int s = 0, sF = 0;
#pragma unroll
        for (int w = 0; w < 8; w++) { s += sw[w]; sF += swF[w]; }
        g_cnt[b] = s; g_cntF[b] = sF;
    }
}

// ---------------- K2: single-block exclusive scan over block counts ----------------
__global__ void scan_kernel(int B, float* __restrict__ out, size_t R) {
    __shared__ int ts[SCAN_T], tsF[SCAN_T];
    int t = threadIdx.x;
    const int PER = 2;                 // up to 2048 blocks
    int v[PER], vF[PER];
    int s = 0, sF = 0;
#pragma unroll
    for (int k = 0; k < PER; k++) {
        int i = t * PER + k;
        v[k]  = (i < B) ? g_cnt[i]  : 0;
        vF[k] = (i < B) ? g_cntF[i] : 0;
        s += v[k]; sF += vF[k];
    }
    ts[t] = s; tsF[t] = sF;
    __syncthreads();
    for (int off = 1; off < SCAN_T; off <<= 1) {
        int a  = (t >= off) ? ts[t - off]  : 0;
        int aF = (t >= off) ? tsF[t - off] : 0;
        __syncthreads();
        ts[t] += a; tsF[t] += aF;
        __syncthreads();
    }
    int run  = ts[t]  - s;
    int runF = tsF[t] - sF;
#pragma unroll
    for (int k = 0; k < PER; k++) {
        int i = t * PER + k;
        if (i < B) {
            g_off[i]  = run;  run  += v[k];
            g_offF[i] = runF; runF += vF[k];
        }
    }
    if (t == SCAN_T - 1) {
        g_total[0] = ts[t];
        g_total[1] = tsF[t];
        out[11 * R + 0] = (float)ts[t];
        out[11 * R + 1] = (float)tsF[t];
    }
}

// ---------------- K3: stable scatter (smem tile + parallel offset scan) ----------------
__global__ void __launch_bounds__(THREADS)
scatter_kernel(const float2* __restrict__ det2, float* __restrict__ out,
               int R, unsigned roisN) {
    __shared__ float2   srow[TILE * 3];                 // 48 KB
    __shared__ unsigned sm[ITERS * 8], smF[ITERS * 8];  // chunk ballots (row order)
    __shared__ unsigned co[ITERS * 8], coF[ITERS * 8];  // chunk exclusive offsets

    int b = blockIdx.x, t = threadIdx.x;
    int lane = t & 31, warp = t >> 5;
    unsigned ltmask = (1u << lane) - 1u;
    int base = b * TILE;

    // phase 1: load tile, ballot
#pragma unroll
    for (int k = 0; k < ITERS; k++) {
        int idx = base + k * THREADS + t;
        float2 p0 = make_float2(1.f, 0.f);
        float2 p1 = make_float2(0.f, 0.f);
        float2 p2 = make_float2(0.f, -1.f);
        if (idx < R) {
            const float2* r = det2 + (size_t)idx * 3;
            p0 = __ldg(r + 0); p1 = __ldg(r + 1); p2 = __ldg(r + 2);
        }
        int lr = k * THREADS + t;
        srow[lr * 3 + 0] = p0;
        srow[lr * 3 + 1] = p1;
        srow[lr * 3 + 2] = p2;
        bool predF = (idx < R) && (p2.y >= SCORE_THRESHOLD);
        bool pred  = predF && (p0.x == 0.0f);
        unsigned m  = __ballot_sync(0xffffffffu, pred);
        unsigned mF = __ballot_sync(0xffffffffu, predF);
        if (lane == 0) { sm[k * 8 + warp] = m; smF[k * 8 + warp] = mF; }
    }
    __syncthreads();

    // phase 2: two warps compute 64 chunk offsets each via shfl scan
    if (warp == 0) {
        unsigned a0 = __popc(sm[2 * lane]);
        unsigned a1 = __popc(sm[2 * lane + 1]);
        unsigned s = a0 + a1;
#pragma unroll
        for (int o = 1; o < 32; o <<= 1) {
            unsigned n = __shfl_up_sync(0xffffffffu, s, o);
            if (lane >= o) s += n;
        }
        unsigned excl = s - (a0 + a1);
        unsigned basep = (unsigned)g_off[b];
        co[2 * lane]     = basep + excl;
        co[2 * lane + 1] = basep + excl + a0;
    } else if (warp == 1) {
        unsigned a0 = __popc(smF[2 * lane]);
        unsigned a1 = __popc(smF[2 * lane + 1]);
        unsigned s = a0 + a1;
#pragma unroll
        for (int o = 1; o < 32; o <<= 1) {
            unsigned n = __shfl_up_sync(0xffffffffu, s, o);
            if (lane >= o) s += n;
        }
        unsigned excl = s - (a0 + a1);
        unsigned basep = (unsigned)g_offF[b];
        coF[2 * lane]     = basep + excl;
        coF[2 * lane + 1] = basep + excl + a0;
    }
    __syncthreads();

    // phase 3: scatter
    float* __restrict__ outFull = out + roisN;
#pragma unroll
    for (int k = 0; k < ITERS; k++) {
        unsigned m  = sm [k * 8 + warp];
        unsigned mF = smF[k * 8 + warp];
        if ((mF >> lane) & 1u) {
            int lr = k * THREADS + t;
            float2 p0 = srow[lr * 3 + 0];
            float2 p1 = srow[lr * 3 + 1];
            float2 p2 = srow[lr * 3 + 2];
            unsigned posF = coF[k * 8 + warp] + __popc(mF & ltmask);
            float2* oF = reinterpret_cast<float2*>(outFull) + (size_t)posF * 3;
            oF[0] = p0; oF[1] = p1; oF[2] = p2;
            if ((m >> lane) & 1u) {
                unsigned pos = co[k * 8 + warp] + __popc(m & ltmask);
                float* o = out + (size_t)pos * 5;
                o[0] = 0.0f;
                o[1] = p0.y; o[2] = p1.x; o[3] = p1.y; o[4] = p2.x;
            }
        }
    }
}

// ---------------- K4: zero the dynamic tails ----------------
__global__ void __launch_bounds__(THREADS)
zero_tail_kernel(float* __restrict__ out, unsigned R) {
    unsigned roisN = 5u * R;
    unsigned fullN = 6u * R;
    unsigned blockBase = blockIdx.x * 4096u;
    const float4 z4 = make_float4(0.f, 0.f, 0.f, 0.f);

#pragma unroll
    for (int j = 0; j < 4; j++) {
        unsigned f = blockBase + (unsigned)j * 1024u + threadIdx.x * 4u;
        if (f < roisN) {
            unsigned zs = (unsigned)g_total[0] * 5u;
            if (f + 4u <= zs) continue;
            if (f >= zs) {
                *reinterpret_cast<float4*>(out + f) = z4;
            } else {
                for (unsigned x = zs; x < f + 4u; x++) out[x] = 0.0f;
            }
        } else {
            unsigned g = f - roisN;
            if (g >= fullN) continue;
            unsigned zs = (unsigned)g_total[1] * 6u;
            if (g + 4u <= zs) continue;
            float* o = out + roisN;
            if (g >= zs) {
                *reinterpret_cast<float4*>(o + g) = z4;
            } else {
                for (unsigned x = zs; x < g + 4u; x++) o[x] = 0.0f;
            }
        }
    }
}

// ---------------- launch ----------------
extern "C" void kernel_launch(void* const* d_in, const int* in_sizes, int n_in,
                              void* d_out, int out_size) {
    const float* det = (const float*)d_in[0];
    float* out = (float*)d_out;

    int R = in_sizes[0] / 6;                 // detections: (1, R, 6)
    int B = (R + TILE - 1) / TILE;           // 2048 for R = 4M
    unsigned roisN = 5u * (unsigned)R;

    count_kernel<<<B, THREADS>>>((const float4*)det, R);
    scan_kernel<<<1, SCAN_T>>>(B, out, (size_t)R);
    scatter_kernel<<<B, THREADS>>>((const float2*)det, out, R, roisN);

    unsigned totalFloats = 11u * (unsigned)R;
    unsigned zblocks = (totalFloats + 4095u) / 4096u;
    zero_tail_kernel<<<zblocks, THREADS>>>(out, (unsigned)R);
}

// round 4
// speedup vs baseline: 1.7170x; 1.0124x over previous
#include <cuda_runtime.h>
#include <cuda_bf16.h>
#include <stdint.h>

// ---------------- configuration ----------------
#define THREADS   256
#define TILE      2048                 // rows per block
#define PAIRS     4                    // row-pairs per thread (4*2*256 = 2048)
#define MAXB      16384
#define SCAN_T    1024
#define TH        0.35f

// ---------------- device scratch ----------------
__device__ int g_cnt [MAXB];
__device__ int g_cntF[MAXB];
__device__ int g_off [MAXB];
__device__ int g_offF[MAXB];
__device__ int g_total[2];

// ---------------- K1: per-block counts (float4 streaming) ----------------
__global__ void __launch_bounds__(THREADS)
count_kernel(const float4* __restrict__ q, int R) {
    int b = blockIdx.x, t = threadIdx.x;
    int pairBase = b * (TILE / 2);
    int c = 0, cF = 0;
#pragma unroll
    for (int k = 0; k < PAIRS; k++) {
        int p = pairBase + k * THREADS + t;
        int r0 = p * 2;
        if (r0 < R) {
            const float4* g = q + (size_t)p * 3;
            float4 q0 = __ldg(g + 0);
            float4 q1 = __ldg(g + 1);
            float4 q2 = __ldg(g + 2);
            bool f0 = (q1.y >= TH);
            bool f1 = (r0 + 1 < R) && (q2.w >= TH);
            cF += (f0 ? 1 : 0) + (f1 ? 1 : 0);
            c  += ((f0 && q0.x == 0.0f) ? 1 : 0) + ((f1 && q1.z == 0.0f) ? 1 : 0);
        }
    }
#pragma unroll
    for (int o = 16; o > 0; o >>= 1) {
        c  += __shfl_down_sync(0xffffffffu, c,  o);
        cF += __shfl_down_sync(0xffffffffu, cF, o);
    }
    __shared__ int sw[8], swF[8];
    int lane = t & 31, warp = t >> 5;
    if (lane == 0) { sw[warp] = c; swF[warp] = cF; }
    __syncthreads();
    if (t == 0) {
        int s = 0, sF = 0;
#pragma unroll
        for (int w = 0; w < 8; w++) { s += sw[w]; sF += swF[w]; }
        g_cnt[b] = s; g_cntF[b] = sF;
    }
}

// ---------------- K2: single-block exclusive scan over block counts ----------------
__global__ void scan_kernel(int B, float* __restrict__ out, size_t R) {
    __shared__ int ts[SCAN_T], tsF[SCAN_T];
    int t = threadIdx.x;
    const int PER = 2;
    int v[PER], vF[PER];
    int s = 0, sF = 0;
#pragma unroll
    for (int k = 0; k < PER; k++) {
        int i = t * PER + k;
        v[k]  = (i < B) ? g_cnt[i]  : 0;
        vF[k] = (i < B) ? g_cntF[i] : 0;
        s += v[k]; sF += vF[k];
    }
    ts[t] = s; tsF[t] = sF;
    __syncthreads();
    for (int off = 1; off < SCAN_T; off <<= 1) {
        int a  = (t >= off) ? ts[t - off]  : 0;
        int aF = (t >= off) ? tsF[t - off] : 0;
        __syncthreads();
        ts[t] += a; tsF[t] += aF;
        __syncthreads();
    }
    int run  = ts[t]  - s;
    int runF = tsF[t] - sF;
#pragma unroll
    for (int k = 0; k < PER; k++) {
        int i = t * PER + k;
        if (i < B) {
            g_off[i]  = run;  run  += v[k];
            g_offF[i] = runF; runF += vF[k];
        }
    }
    if (t == SCAN_T - 1) {
        g_total[0] = ts[t];
        g_total[1] = tsF[t];
        out[11 * R + 0] = (float)ts[t];
        out[11 * R + 1] = (float)tsF[t];
    }
}

// ---------------- K3: fused stable scatter + tail zero ----------------
__global__ void __launch_bounds__(THREADS)
scatter_zero_kernel(const float4* __restrict__ q, float* __restrict__ out,
                    int R, unsigned roisN, unsigned quadsPerBlock) {
    __shared__ unsigned mlo[PAIRS][8], mhi[PAIRS][8];
    __shared__ unsigned mloF[PAIRS][8], mhiF[PAIRS][8];
    __shared__ unsigned co[PAIRS * 8], coF[PAIRS * 8];

    int b = blockIdx.x, t = threadIdx.x;
    int lane = t & 31, warp = t >> 5;
    unsigned lt = (1u << lane) - 1u;
    int pairBase = b * (TILE / 2);

    // -------- phase 1: load pairs into registers, ballot --------
    float4 v0[PAIRS], v1[PAIRS], v2[PAIRS];
#pragma unroll
    for (int k = 0; k < PAIRS; k++) {
        int p = pairBase + k * THREADS + t;
        int r0 = 2 * p;
        float4 a = make_float4(1.f, 0.f, 0.f, 0.f);
        float4 c = make_float4(0.f, -1.f, 1.f, 0.f);
        float4 d = make_float4(0.f, 0.f, 0.f, -1.f);
        if (r0 < R) {
            const float4* g = q + (size_t)p * 3;
            a = __ldg(g + 0); c = __ldg(g + 1); d = __ldg(g + 2);
        }
        v0[k] = a; v1[k] = c; v2[k] = d;
        // pair = [cls0,b00,b01,b02 | b03,sc0, cls1,b10 | b11,b12,b13,sc1]
        bool f0 = (r0 < R)     && (c.y >= TH);
        bool f1 = (r0 + 1 < R) && (d.w >= TH);
        bool p0 = f0 && (a.x == 0.0f);
        bool p1 = f1 && (c.z == 0.0f);
        unsigned blo  = __ballot_sync(0xffffffffu, p0);
        unsigned bhi  = __ballot_sync(0xffffffffu, p1);
        unsigned bFlo = __ballot_sync(0xffffffffu, f0);
        unsigned bFhi = __ballot_sync(0xffffffffu, f1);
        if (lane == 0) {
            mlo[k][warp] = blo;   mhi[k][warp] = bhi;
            mloF[k][warp] = bFlo; mhiF[k][warp] = bFhi;
        }
    }
    __syncthreads();

    // -------- phase 2: two warps compute all 32 chunk offsets --------
    if (warp == 0) {                 // target counter
        int k = lane >> 3, w = lane & 7;
        unsigned cnt = __popc(mlo[k][w]) + __popc(mhi[k][w]);
        unsigned s = cnt;
#pragma unroll
        for (int o = 1; o < 32; o <<= 1) {
            unsigned n = __shfl_up_sync(0xffffffffu, s, o);
            if (lane >= o) s += n;
        }
        co[lane] = (unsigned)g_off[b] + s - cnt;
    } else if (warp == 1) {          // full counter
        int k = lane >> 3, w = lane & 7;
        unsigned cnt = __popc(mloF[k][w]) + __popc(mhiF[k][w]);
        unsigned s = cnt;
#pragma unroll
        for (int o = 1; o < 32; o <<= 1) {
            unsigned n = __shfl_up_sync(0xffffffffu, s, o);
            if (lane >= o) s += n;
        }
        coF[lane] = (unsigned)g_offF[b] + s - cnt;
    }
    __syncthreads();

    // -------- phase 3: scatter from registers --------
    float2* __restrict__ outFull2 = reinterpret_cast<float2*>(out + roisN);
#pragma unroll
    for (int k = 0; k < PAIRS; k++) {
        unsigned blo  = mlo[k][warp],  bhi  = mhi[k][warp];
        unsigned bFlo = mloF[k][warp], bFhi = mhiF[k][warp];
        unsigned baseT = co[k * 8 + warp], baseF = coF[k * 8 + warp];
        unsigned preT = __popc(blo & lt) + __popc(bhi & lt);
        unsigned preF = __popc(bFlo & lt) + __popc(bFhi & lt);
        float4 a = v0[k], c = v1[k], d = v2[k];
        // row 0
        if ((bFlo >> lane) & 1u) {
            float2* oF = outFull2 + (size_t)(baseF + preF) * 3;
            oF[0] = make_float2(a.x, a.y);
            oF[1] = make_float2(a.z, a.w);
            oF[2] = make_float2(c.x, c.y);
            if ((blo >> lane) & 1u) {
                float* o = out + (size_t)(baseT + preT) * 5;
                o[0] = 0.0f; o[1] = a.y; o[2] = a.z; o[3] = a.w; o[4] = c.x;
            }
        }
        // row 1
        if ((bFhi >> lane) & 1u) {
            unsigned posF = baseF + preF + ((bFlo >> lane) & 1u);
            float2* oF = outFull2 + (size_t)posF * 3;
            oF[0] = make_float2(c.z, c.w);
            oF[1] = make_float2(d.x, d.y);
            oF[2] = make_float2(d.z, d.w);
            if ((bhi >> lane) & 1u) {
                unsigned pos = baseT + preT + ((blo >> lane) & 1u);
                float* o = out + (size_t)pos * 5;
                o[0] = 0.0f; o[1] = c.w; o[2] = d.x; o[3] = d.y; o[4] = d.z;
            }
        }
    }

    // -------- phase 4: zero this block's share of the tails --------
    unsigned fullN = (roisN / 5u) * 6u;
    unsigned zsT = (unsigned)g_total[0] * 5u;
    unsigned zsF = (unsigned)g_total[1] * 6u;
    unsigned qEnd = (unsigned)b * quadsPerBlock + quadsPerBlock;
    const float4 z4 = make_float4(0.f, 0.f, 0.f, 0.f);
    for (unsigned qi = (unsigned)b * quadsPerBlock + t; qi < qEnd; qi += THREADS) {
        unsigned f = qi * 4u;
        if (f < roisN) {
            if (f + 4u <= zsT) continue;
            if (f >= zsT) {
                *reinterpret_cast<float4*>(out + f) = z4;
            } else {
                for (unsigned x = zsT; x < f + 4u; x++) out[x] = 0.0f;
            }
        } else {
            unsigned g = f - roisN;
            if (g >= fullN) break;
            if (g + 4u <= zsF) continue;
            float* o = out + roisN;
            if (g >= zsF) {
                *reinterpret_cast<float4*>(o + g) = z4;
            } else {
                for (unsigned x = zsF; x < g + 4u; x++) o[x] = 0.0f;
            }
        }
    }
}

// ---------------- launch ----------------
extern "C" void kernel_launch(void* const* d_in, const int* in_sizes, int n_in,
                              void* d_out, int out_size) {
    const float* det = (const float*)d_in[0];
    float* out = (float*)d_out;

    int R = in_sizes[0] / 6;                 // detections: (1, R, 6)
    int B = (R + TILE - 1) / TILE;           // 2048 for R = 4M
    unsigned roisN = 5u * (unsigned)R;

    unsigned totalQuads = (11u * (unsigned)R + 3u) / 4u;
    unsigned quadsPerBlock = (totalQuads + (unsigned)B - 1u) / (unsigned)B;

    count_kernel<<<B, THREADS>>>((const float4*)det, R);
    scan_kernel<<<1, SCAN_T>>>(B, out, (size_t)R);
    scatter_zero_kernel<<<B, THREADS>>>((const float4*)det, out, R, roisN, quadsPerBlock);
}

// round 5
// speedup vs baseline: 2.0193x; 1.1761x over previous
#include <cuda_runtime.h>
#include <cuda_bf16.h>
#include <stdint.h>

// ---------------- configuration ----------------
#define THREADS   256
#define TILE      2048                 // rows per block
#define PAIRS     4                    // row-pairs per thread (4*2*256 = 2048)
#define MAXB      16384
#define TH        0.35f

#define FLAG_A    (1u << 30)           // aggregate ready
#define FLAG_P    (2u << 30)           // prefix ready
#define VALMASK   0x3FFFFFFFu

// ---------------- device scratch ----------------
// lookback status: [31:30]=flag, [29:0]=count. Zeroed by zero_tail for next replay.
__device__ unsigned g_stat [MAXB];
__device__ unsigned g_statF[MAXB];
__device__ int      g_total[2];

// ---------------- K1: fused count + decoupled-lookback scan + stable scatter ----------------
__global__ void __launch_bounds__(THREADS)
fused_kernel(const float4* __restrict__ q, float* __restrict__ out,
             int R, unsigned roisN, int B) {
    __shared__ unsigned mlo[PAIRS][8], mhi[PAIRS][8];
    __shared__ unsigned mloF[PAIRS][8], mhiF[PAIRS][8];
    __shared__ unsigned co[32], coF[32];

    int b = blockIdx.x, t = threadIdx.x;
    int lane = t & 31, warp = t >> 5;
    unsigned lt = (1u << lane) - 1u;
    int pairBase = b * (TILE / 2);

    // -------- phase 1: load pairs into registers, ballot --------
    float4 v0[PAIRS], v1[PAIRS], v2[PAIRS];
#pragma unroll
    for (int k = 0; k < PAIRS; k++) {
        int p = pairBase + k * THREADS + t;
        int r0 = 2 * p;
        float4 a = make_float4(1.f, 0.f, 0.f, 0.f);
        float4 c = make_float4(0.f, -1.f, 1.f, 0.f);
        float4 d = make_float4(0.f, 0.f, 0.f, -1.f);
        if (r0 < R) {
            const float4* g = q + (size_t)p * 3;
            a = __ldg(g + 0); c = __ldg(g + 1); d = __ldg(g + 2);
        }
        v0[k] = a; v1[k] = c; v2[k] = d;
        // pair = [cls0,b00,b01,b02 | b03,sc0, cls1,b10 | b11,b12,b13,sc1]
        bool f0 = (r0 < R)     && (c.y >= TH);
        bool f1 = (r0 + 1 < R) && (d.w >= TH);
        bool p0 = f0 && (a.x == 0.0f);
        bool p1 = f1 && (c.z == 0.0f);
        unsigned blo  = __ballot_sync(0xffffffffu, p0);
        unsigned bhi  = __ballot_sync(0xffffffffu, p1);
        unsigned bFlo = __ballot_sync(0xffffffffu, f0);
        unsigned bFhi = __ballot_sync(0xffffffffu, f1);
        if (lane == 0) {
            mlo[k][warp] = blo;   mhi[k][warp] = bhi;
            mloF[k][warp] = bFlo; mhiF[k][warp] = bFhi;
        }
    }
    __syncthreads();

    // -------- phase 2: warps 0/1 do local scan + warp-parallel lookback --------
    if (warp < 2) {
        unsigned* stat = (warp == 0) ? g_stat : g_statF;
        int k = lane >> 3, w = lane & 7;
        unsigned cnt = (warp == 0)
            ? (__popc(mlo[k][w])  + __popc(mhi[k][w]))
            : (__popc(mloF[k][w]) + __popc(mhiF[k][w]));
        // inclusive shfl scan over 32 chunks
        unsigned s = cnt;
#pragma unroll
        for (int o = 1; o < 32; o <<= 1) {
            unsigned n = __shfl_up_sync(0xffffffffu, s, o);
            if (lane >= o) s += n;
        }
        unsigned agg = __shfl_sync(0xffffffffu, s, 31);

        unsigned excl = 0;
        if (b == 0) {
            if (lane == 0) atomicExch(&stat[0], FLAG_P | agg);
        } else {
            if (lane == 0) atomicExch(&stat[b], FLAG_A | agg);
            int idx = b - 1 - lane;            // lane 0 = closest predecessor
            for (;;) {
                unsigned s2;
                if (idx >= 0) {
                    do { s2 = *(volatile unsigned*)&stat[idx]; }
                    while ((s2 >> 30) == 0u);
                } else {
                    s2 = FLAG_P;               // virtual prefix 0 before block 0
                }
                unsigned pmask = __ballot_sync(0xffffffffu, (s2 >> 30) == 2u);
                if (pmask) {
                    int first = __ffs(pmask) - 1;   // closest prefix
                    unsigned v = (lane <= first) ? (s2 & VALMASK) : 0u;
                    excl += __reduce_add_sync(0xffffffffu, v);
                    break;
                } else {
                    excl += __reduce_add_sync(0xffffffffu, s2 & VALMASK);
                    idx -= 32;
                }
            }
            if (lane == 0) atomicExch(&stat[b], FLAG_P | (excl + agg));
        }
        unsigned* dst = (warp == 0) ? co : coF;
        dst[lane] = excl + s - cnt;            // block-global exclusive chunk offset
        if (b == B - 1 && lane == 0) {
            unsigned total = excl + agg;
            g_total[warp] = (int)total;
            out[11u * (size_t)(roisN / 5u) + warp] = (float)total;
        }
    }
    __syncthreads();

    // -------- phase 3: stable scatter from registers --------
    float2* __restrict__ outFull2 = reinterpret_cast<float2*>(out + roisN);
#pragma unroll
    for (int k = 0; k < PAIRS; k++) {
        unsigned blo  = mlo[k][warp],  bhi  = mhi[k][warp];
        unsigned bFlo = mloF[k][warp], bFhi = mhiF[k][warp];
        unsigned baseT = co[k * 8 + warp], baseF = coF[k * 8 + warp];
        unsigned preT = __popc(blo & lt) + __popc(bhi & lt);
        unsigned preF = __popc(bFlo & lt) + __popc(bFhi & lt);
        float4 a = v0[k], c = v1[k], d = v2[k];
        // row 0 of pair
        if ((bFlo >> lane) & 1u) {
            float2* oF = outFull2 + (size_t)(baseF + preF) * 3;
            oF[0] = make_float2(a.x, a.y);
            oF[1] = make_float2(a.z, a.w);
            oF[2] = make_float2(c.x, c.y);
            if ((blo >> lane) & 1u) {
                float* o = out + (size_t)(baseT + preT) * 5;
                o[0] = 0.0f; o[1] = a.y; o[2] = a.z; o[3] = a.w; o[4] = c.x;
            }
        }
        // row 1 of pair
        if ((bFhi >> lane) & 1u) {
            unsigned posF = baseF + preF + ((bFlo >> lane) & 1u);
            float2* oF = outFull2 + (size_t)posF * 3;
            oF[0] = make_float2(c.z, c.w);
            oF[1] = make_float2(d.x, d.y);
            oF[2] = make_float2(d.z, d.w);
            if ((bhi >> lane) & 1u) {
                unsigned pos = baseT + preT + ((blo >> lane) & 1u);
                float* o = out + (size_t)pos * 5;
                o[0] = 0.0f; o[1] = c.w; o[2] = d.x; o[3] = d.y; o[4] = d.z;
            }
        }
    }
}

// ---------------- K2: zero the dynamic tails + reset lookback state ----------------
__global__ void __launch_bounds__(THREADS)
zero_tail_kernel(float* __restrict__ out, unsigned R, int B) {
    unsigned roisN = 5u * R;
    unsigned fullN = 6u * R;
    unsigned blockBase = blockIdx.x * 4096u;
    const float4 z4 = make_float4(0.f, 0.f, 0.f, 0.f);
    unsigned zsT = (unsigned)g_total[0] * 5u;
    unsigned zsF = (unsigned)g_total[1] * 6u;

#pragma unroll
    for (int j = 0; j < 4; j++) {
        unsigned f = blockBase + (unsigned)j * 1024u + threadIdx.x * 4u;
        if (f < roisN) {
            if (f + 4u <= zsT) continue;
            if (f >= zsT) {
                *reinterpret_cast<float4*>(out + f) = z4;
            } else {
                for (unsigned x = zsT; x < f + 4u; x++) out[x] = 0.0f;
            }
        } else {
            unsigned g = f - roisN;
            if (g >= fullN) continue;
            if (g + 4u <= zsF) continue;
            float* o = out + roisN;
            if (g >= zsF) {
                *reinterpret_cast<float4*>(o + g) = z4;
            } else {
                for (unsigned x = zsF; x < g + 4u; x++) o[x] = 0.0f;
            }
        }
    }
    // reset lookback statuses for the next replay (stream-ordered after fused)
    int gi = blockIdx.x * THREADS + threadIdx.x;
    if (gi < B) { g_stat[gi] = 0u; g_statF[gi] = 0u; }
}

// ---------------- launch ----------------
extern "C" void kernel_launch(void* const* d_in, const int* in_sizes, int n_in,
                              void* d_out, int out_size) {
    const float* det = (const float*)d_in[0];
    float* out = (float*)d_out;

    int R = in_sizes[0] / 6;                 // detections: (1, R, 6)
    int B = (R + TILE - 1) / TILE;           // 2048 for R = 4M
    unsigned roisN = 5u * (unsigned)R;

    fused_kernel<<<B, THREADS>>>((const float4*)det, out, R, roisN, B);

    unsigned totalFloats = 11u * (unsigned)R;
    unsigned zblocks = (totalFloats + 4095u) / 4096u;
    zero_tail_kernel<<<zblocks, THREADS>>>(out, (unsigned)R, B);
}